// round 11
// baseline (speedup 1.0000x reference)
#include <cuda_runtime.h>
#include <cstdint>

#define DD 8
#define BB 8
#define NN 2048
#define NN2 (NN * NN)        // 4194304

// 64-bit spike mask per presynaptic neuron e: bit (d*8+b) set iff Xd[d,b,e]==1
__device__ unsigned long long g_spike[NN];

// ---------------------------------------------------------------------------
// Kernel 1: ballot-pack spike masks (one warp per e) + zero output.
//   256 CTAs x 8 warps = 2048 warps = one per e. Lane loads Xd[db, e] for
//   db=lane and db=lane+32 (L2-resident gathers), two ballots -> 64-bit mask.
// ---------------------------------------------------------------------------
__global__ void __launch_bounds__(256)
pack_kernel(const float* __restrict__ Xd, float* __restrict__ out) {
    const int gid  = blockIdx.x * 256 + threadIdx.x;
    const int lane = threadIdx.x & 31;
    const int e    = gid >> 5;                       // global warp id = e

    const bool s0 = Xd[(size_t)lane        * NN + e] > 0.5f;
    const bool s1 = Xd[(size_t)(lane + 32) * NN + e] > 0.5f;
    const unsigned lo = __ballot_sync(0xFFFFFFFFu, s0);
    const unsigned hi = __ballot_sync(0xFFFFFFFFu, s1);
    if (lane == 0)
        g_spike[e] = (unsigned long long)lo | ((unsigned long long)hi << 32);

    if (gid < BB * NN) out[gid] = 0.0f;
}

// ---------------------------------------------------------------------------
// Kernel 2: fused gate + blend + reduce over 32e x 32o tiles.
//   Phase A1 (per warp, 4 e-rows): read spike mask, then ONLY the active
//     delay planes' 128B row segments of delaymap (~2.7/8 planes) -> gate
//     bytes into smem. One-hot => gate byte = batch mask of matching delay.
//   Phase A2 (all threads): statics float4 streams -> precomputed (cs,cp).
//   Phase B (warp = batch): per iter 1 LDS.64 + 1 LDS.32 + @P Wlong LDG.32.
// ---------------------------------------------------------------------------
#define ET 32
#define OT 32

__global__ void __launch_bounds__(256)
fused_kernel(const float*  __restrict__ dm,    // delaymap (D,N,N)
             const float4* __restrict__ W4,    // (N,N)
             const float*  __restrict__ Wl,    // Wlong (B,N,N)
             const float4* __restrict__ F4,    // STDP_frac (N,N)
             const float4* __restrict__ S4,    // signs (N,N)
             float* __restrict__ out)          // (B,N)
{
    __shared__ float2   sCP[ET][OT];   // (cs, cp) per (e,o)
    __shared__ unsigned sG[ET][OT];    // gate byte per (e,o)

    const int t     = threadIdx.x;
    const int lane  = t & 31;
    const int w     = t >> 5;
    const int obase = blockIdx.x * OT;
    const int ebase = blockIdx.y * ET;

    // ---- Phase A1: gates for rows 4w .. 4w+3 ----
#pragma unroll
    for (int r = 0; r < 4; r++) {
        const int el = w * 4 + r;
        const int e  = ebase + el;
        const unsigned long long bits = g_spike[e];   // uniform 8B load (L2)
        unsigned gate = 0;
#pragma unroll
        for (int d = 0; d < DD; d++) {
            const unsigned m8 = (unsigned)(bits >> (d * 8)) & 0xFFu;
            if (m8) {                                 // warp-uniform branch
                const float v = dm[((size_t)d * NN + e) * NN + obase + lane];
                if (v > 0.5f) gate = m8;              // one-hot: <=1 match
            }
        }
        sG[el][lane] = gate;
    }

    // ---- Phase A2: statics -> (cs, cp) ----
    {
        const int ee = t >> 3;                        // 0..31
        const int qq = t & 7;                         // quad in row
        const size_t g4 = ((size_t)(ebase + ee) * NN + obase) / 4 + qq;
        const float4 s = S4[g4];
        const float4 wv = W4[g4];
        const float4 f = F4[g4];
        sCP[ee][qq * 4 + 0] = make_float2(s.x * wv.x * (1.0f - f.x), s.x * f.x);
        sCP[ee][qq * 4 + 1] = make_float2(s.y * wv.y * (1.0f - f.y), s.y * f.y);
        sCP[ee][qq * 4 + 2] = make_float2(s.z * wv.z * (1.0f - f.z), s.z * f.z);
        sCP[ee][qq * 4 + 3] = make_float2(s.w * wv.w * (1.0f - f.w), s.w * f.w);
    }
    __syncthreads();

    // ---- Phase B: warp = batch b over 32 o ----
    const int b = w;
    const float* __restrict__ wlp =
        Wl + (size_t)b * NN2 + (size_t)ebase * NN + obase + lane;

    float acc = 0.0f;
#pragma unroll 8
    for (int ee = 0; ee < ET; ee++) {
        const unsigned g = sG[ee][lane];
        const bool on = (g >> b) & 1u;
        const float2 cp = sCP[ee][lane];
        float wl = 0.0f;
        if (on) wl = wlp[(size_t)ee * NN];            // sole DRAM access
        if (on) acc += fmaf(cp.y, wl, cp.x);          // cs + cp*wl
    }

    atomicAdd(&out[b * NN + obase + lane], acc);
}

// ---------------------------------------------------------------------------
// Launch
// ---------------------------------------------------------------------------
extern "C" void kernel_launch(void* const* d_in, const int* in_sizes, int n_in,
                              void* d_out, int out_size) {
    const float* Xd = (const float*)d_in[0];   // (D,B,N)
    const float* dm = (const float*)d_in[1];   // (D,N,N)
    const float* W  = (const float*)d_in[2];   // (N,N)
    const float* Wl = (const float*)d_in[3];   // (B,N,N)
    const float* F  = (const float*)d_in[4];   // (N,N)
    const float* S  = (const float*)d_in[5];   // (N,N)
    float* out = (float*)d_out;                // (B,N)

    pack_kernel<<<(NN * 32) / 256, 256>>>(Xd, out);   // 256 CTAs

    dim3 grid(NN / OT, NN / ET);                      // 64 x 64 = 4096 CTAs
    fused_kernel<<<grid, 256>>>(dm, (const float4*)W, Wl,
                                (const float4*)F, (const float4*)S, out);
}

// round 12
// speedup vs baseline: 1.0993x; 1.0993x over previous
#include <cuda_runtime.h>
#include <cstdint>

#define DD 8
#define BB 8
#define NN 2048
#define NN2 (NN * NN)        // 4194304

// 64-bit spike mask per presynaptic neuron e: bit (d*8+b) set iff Xd[d,b,e]==1
__device__ unsigned long long g_spike[NN];

// ---------------------------------------------------------------------------
// Kernel 1: ballot-pack spike masks (one warp per e) + zero output.
// ---------------------------------------------------------------------------
__global__ void __launch_bounds__(256)
pack_kernel(const float* __restrict__ Xd, float* __restrict__ out) {
    const int gid  = blockIdx.x * 256 + threadIdx.x;
    const int lane = threadIdx.x & 31;
    const int e    = gid >> 5;                       // global warp id = e

    const bool s0 = Xd[(size_t)lane        * NN + e] > 0.5f;
    const bool s1 = Xd[(size_t)(lane + 32) * NN + e] > 0.5f;
    const unsigned lo = __ballot_sync(0xFFFFFFFFu, s0);
    const unsigned hi = __ballot_sync(0xFFFFFFFFu, s1);
    if (lane == 0)
        g_spike[e] = (unsigned long long)lo | ((unsigned long long)hi << 32);

    if (gid < BB * NN) out[gid] = 0.0f;
}

// ---------------------------------------------------------------------------
// Kernel 2: fused gate + blend + reduce over 16e x 128o tiles.
//   Phase A1 (warp -> 2 e-rows): spike-mask-gated delaymap read (~2.7/8
//     planes), one float4 (o-quad) per lane -> packed gate word in smem.
//   Phase A2: statics float4 streams -> cs/cp arrays in smem.
//   Phase B (warp = batch b, lane = o-quad): per iter 1 LDS.32 gate word +
//     2 LDS.128 coeffs + union-predicated Wlong LDG.128 + 8 predicated FMAs
//     = ~25 instr per 128 cells (4x fewer instructions than R11).
//     Union predicate is DRAM-traffic-neutral at 32B sector granularity.
// ---------------------------------------------------------------------------
#define ET 16
#define OT 128

__global__ void __launch_bounds__(256)
fused_kernel(const float4* __restrict__ dm4,   // delaymap (D,N,N)
             const float4* __restrict__ W4,    // (N,N)
             const float*  __restrict__ Wl,    // Wlong (B,N,N)
             const float4* __restrict__ F4,    // STDP_frac (N,N)
             const float4* __restrict__ S4,    // signs (N,N)
             float* __restrict__ out)          // (B,N)
{
    __shared__ float    sCS[ET][OT];       // 8 KB
    __shared__ float    sCP[ET][OT];       // 8 KB
    __shared__ unsigned sG[ET][OT / 4];    // 2 KB packed gate words

    const int t     = threadIdx.x;
    const int lane  = t & 31;
    const int w     = t >> 5;
    const int obase = blockIdx.x * OT;
    const int ebase = blockIdx.y * ET;

    // ---- Phase A1: gates; warp handles rows 2w, 2w+1; lane -> o-quad ----
#pragma unroll
    for (int r = 0; r < 2; r++) {
        const int el = w * 2 + r;
        const int e  = ebase + el;
        const unsigned long long bits = g_spike[e];   // uniform (L2-resident)
        unsigned g0 = 0, g1 = 0, g2 = 0, g3 = 0;
#pragma unroll
        for (int d = 0; d < DD; d++) {
            const unsigned m8 = (unsigned)(bits >> (d * 8)) & 0xFFu;
            if (m8) {                                 // warp-uniform branch
                const float4 v =
                    dm4[((size_t)d * NN + e) * (NN / 4) + obase / 4 + lane];
                if (v.x > 0.5f) g0 = m8;              // one-hot: <=1 match
                if (v.y > 0.5f) g1 = m8;
                if (v.z > 0.5f) g2 = m8;
                if (v.w > 0.5f) g3 = m8;
            }
        }
        sG[el][lane] = g0 | (g1 << 8) | (g2 << 16) | (g3 << 24);
    }

    // ---- Phase A2: statics -> cs/cp (512 float4 per array, 2 per thread) ----
#pragma unroll
    for (int k = 0; k < 2; k++) {
        const int idx = t + k * 256;                  // float4 index in tile
        const int ee  = idx >> 5;                     // 32 quads per row
        const int qq  = idx & 31;
        const size_t g4 = ((size_t)(ebase + ee) * NN + obase) / 4 + qq;
        const float4 s = S4[g4];
        const float4 wv = W4[g4];
        const float4 f = F4[g4];
        sCS[ee][qq * 4 + 0] = s.x * wv.x * (1.0f - f.x);
        sCS[ee][qq * 4 + 1] = s.y * wv.y * (1.0f - f.y);
        sCS[ee][qq * 4 + 2] = s.z * wv.z * (1.0f - f.z);
        sCS[ee][qq * 4 + 3] = s.w * wv.w * (1.0f - f.w);
        sCP[ee][qq * 4 + 0] = s.x * f.x;
        sCP[ee][qq * 4 + 1] = s.y * f.y;
        sCP[ee][qq * 4 + 2] = s.z * f.z;
        sCP[ee][qq * 4 + 3] = s.w * f.w;
    }
    __syncthreads();

    // ---- Phase B: warp = batch b; lane = o-quad ----
    const int b = w;
    const float4* __restrict__ wlb = (const float4*)(Wl + (size_t)b * NN2)
                                   + ((size_t)ebase * NN + obase) / 4 + lane;

    float a0 = 0.f, a1 = 0.f, a2 = 0.f, a3 = 0.f;
#pragma unroll
    for (int ee = 0; ee < ET; ee++) {
        const unsigned g  = sG[ee][lane];
        const unsigned un = g | (g >> 8) | (g >> 16) | (g >> 24);
        float4 wl = make_float4(0.f, 0.f, 0.f, 0.f);
        if ((un >> b) & 1u) wl = wlb[(size_t)ee * (NN / 4)];  // @P LDG.128

        const float4 cs = *(const float4*)&sCS[ee][lane * 4];
        const float4 cp = *(const float4*)&sCP[ee][lane * 4];
        a0 += ((g >>  b)        & 1u) ? fmaf(cp.x, wl.x, cs.x) : 0.0f;
        a1 += ((g >> ( 8 + b))  & 1u) ? fmaf(cp.y, wl.y, cs.y) : 0.0f;
        a2 += ((g >> (16 + b))  & 1u) ? fmaf(cp.z, wl.z, cs.z) : 0.0f;
        a3 += ((g >> (24 + b))  & 1u) ? fmaf(cp.w, wl.w, cs.w) : 0.0f;
    }

    float* op = out + b * NN + obase + lane * 4;
    atomicAdd(op + 0, a0);
    atomicAdd(op + 1, a1);
    atomicAdd(op + 2, a2);
    atomicAdd(op + 3, a3);
}

// ---------------------------------------------------------------------------
// Launch
// ---------------------------------------------------------------------------
extern "C" void kernel_launch(void* const* d_in, const int* in_sizes, int n_in,
                              void* d_out, int out_size) {
    const float* Xd = (const float*)d_in[0];   // (D,B,N)
    const float* dm = (const float*)d_in[1];   // (D,N,N)
    const float* W  = (const float*)d_in[2];   // (N,N)
    const float* Wl = (const float*)d_in[3];   // (B,N,N)
    const float* F  = (const float*)d_in[4];   // (N,N)
    const float* S  = (const float*)d_in[5];   // (N,N)
    float* out = (float*)d_out;                // (B,N)

    pack_kernel<<<(NN * 32) / 256, 256>>>(Xd, out);   // 256 CTAs

    dim3 grid(NN / OT, NN / ET);                      // 16 x 128 = 2048 CTAs
    fused_kernel<<<grid, 256>>>((const float4*)dm, (const float4*)W, Wl,
                                (const float4*)F, (const float4*)S, out);
}

// round 13
// speedup vs baseline: 1.1500x; 1.0461x over previous
#include <cuda_runtime.h>
#include <cstdint>

#define DD 8
#define BB 8
#define NN 2048
#define NN2 (NN * NN)        // 4194304

// 64-bit spike mask per presynaptic neuron e: bit (d*8+b) set iff Xd[d,b,e]==1
__device__ unsigned long long g_spike[NN];

// ---------------------------------------------------------------------------
// Kernel 1: ballot-pack spike masks (one warp per e) + zero output.
// ---------------------------------------------------------------------------
__global__ void __launch_bounds__(256)
pack_kernel(const float* __restrict__ Xd, float* __restrict__ out) {
    const int gid  = blockIdx.x * 256 + threadIdx.x;
    const int lane = threadIdx.x & 31;
    const int e    = gid >> 5;                       // global warp id = e

    const bool s0 = Xd[(size_t)lane        * NN + e] > 0.5f;
    const bool s1 = Xd[(size_t)(lane + 32) * NN + e] > 0.5f;
    const unsigned lo = __ballot_sync(0xFFFFFFFFu, s0);
    const unsigned hi = __ballot_sync(0xFFFFFFFFu, s1);
    if (lane == 0)
        g_spike[e] = (unsigned long long)lo | ((unsigned long long)hi << 32);

    if (gid < BB * NN) out[gid] = 0.0f;
}

// ---------------------------------------------------------------------------
// Kernel 2: fused gate + blend + reduce over 16e x 128o tiles.
//   Phase A1 (warp -> 2 e-rows): spike-gated delaymap read (~2.7/8 planes)
//     -> packed gate words + per-row batch-union byte in smem.
//   Phase A2: statics float4 streams -> cs/cp in smem.
//   Phase B (warp = batch b, lane = o-quad): warp-uniform skip of rows where
//     batch b never spiked (P_skip = 0.663). Active rows: unconditional
//     Wlong LDG.128 (sector traffic ~= predicated version) + 2 LDS.128 +
//     1 LDS.32 + 4 gate-predicated FMAs.
// ---------------------------------------------------------------------------
#define ET 16
#define OT 128

__global__ void __launch_bounds__(256)
fused_kernel(const float4* __restrict__ dm4,   // delaymap (D,N,N)
             const float4* __restrict__ W4,    // (N,N)
             const float*  __restrict__ Wl,    // Wlong (B,N,N)
             const float4* __restrict__ F4,    // STDP_frac (N,N)
             const float4* __restrict__ S4,    // signs (N,N)
             float* __restrict__ out)          // (B,N)
{
    __shared__ float    sCS[ET][OT];       // 8 KB
    __shared__ float    sCP[ET][OT];       // 8 KB
    __shared__ unsigned sG[ET][OT / 4];    // 2 KB packed gate words
    __shared__ unsigned sU[ET];            // per-row batch union byte

    const int t     = threadIdx.x;
    const int lane  = t & 31;
    const int w     = t >> 5;
    const int obase = blockIdx.x * OT;
    const int ebase = blockIdx.y * ET;

    // ---- Phase A1: gates + union byte; warp -> rows 2w, 2w+1 ----
#pragma unroll
    for (int r = 0; r < 2; r++) {
        const int el = w * 2 + r;
        const int e  = ebase + el;
        const unsigned long long bits = g_spike[e];   // uniform (L2-resident)
        unsigned g0 = 0, g1 = 0, g2 = 0, g3 = 0;
#pragma unroll
        for (int d = 0; d < DD; d++) {
            const unsigned m8 = (unsigned)(bits >> (d * 8)) & 0xFFu;
            if (m8) {                                 // warp-uniform branch
                const float4 v =
                    dm4[((size_t)d * NN + e) * (NN / 4) + obase / 4 + lane];
                if (v.x > 0.5f) g0 = m8;              // one-hot: <=1 match
                if (v.y > 0.5f) g1 = m8;
                if (v.z > 0.5f) g2 = m8;
                if (v.w > 0.5f) g3 = m8;
            }
        }
        sG[el][lane] = g0 | (g1 << 8) | (g2 << 16) | (g3 << 24);
        if (lane == 0) {
            unsigned long long u = bits | (bits >> 32);
            u |= u >> 16;
            u |= u >> 8;
            sU[el] = (unsigned)u & 0xFFu;             // bit b: batch b spiked at any delay
        }
    }

    // ---- Phase A2: statics -> cs/cp (512 float4 per array, 2 per thread) ----
#pragma unroll
    for (int k = 0; k < 2; k++) {
        const int idx = t + k * 256;                  // float4 index in tile
        const int ee  = idx >> 5;                     // 32 quads per row
        const int qq  = idx & 31;
        const size_t g4 = ((size_t)(ebase + ee) * NN + obase) / 4 + qq;
        const float4 s = S4[g4];
        const float4 wv = W4[g4];
        const float4 f = F4[g4];
        sCS[ee][qq * 4 + 0] = s.x * wv.x * (1.0f - f.x);
        sCS[ee][qq * 4 + 1] = s.y * wv.y * (1.0f - f.y);
        sCS[ee][qq * 4 + 2] = s.z * wv.z * (1.0f - f.z);
        sCS[ee][qq * 4 + 3] = s.w * wv.w * (1.0f - f.w);
        sCP[ee][qq * 4 + 0] = s.x * f.x;
        sCP[ee][qq * 4 + 1] = s.y * f.y;
        sCP[ee][qq * 4 + 2] = s.z * f.z;
        sCP[ee][qq * 4 + 3] = s.w * f.w;
    }
    __syncthreads();

    // ---- Phase B: warp = batch b; lane = o-quad; row-skip on union byte ----
    const int b = w;
    const float4* __restrict__ wlb = (const float4*)(Wl + (size_t)b * NN2)
                                   + ((size_t)ebase * NN + obase) / 4 + lane;

    float a0 = 0.f, a1 = 0.f, a2 = 0.f, a3 = 0.f;
#pragma unroll
    for (int ee = 0; ee < ET; ee++) {
        if (!((sU[ee] >> b) & 1u)) continue;          // warp-uniform skip (P=0.663)

        const unsigned gs = sG[ee][lane] >> b;        // bits 0/8/16/24 = gates
        const float4 wl = wlb[(size_t)ee * (NN / 4)]; // unconditional LDG.128
        const float4 cs = *(const float4*)&sCS[ee][lane * 4];
        const float4 cp = *(const float4*)&sCP[ee][lane * 4];
        a0 += (gs & 0x00000001u) ? fmaf(cp.x, wl.x, cs.x) : 0.0f;
        a1 += (gs & 0x00000100u) ? fmaf(cp.y, wl.y, cs.y) : 0.0f;
        a2 += (gs & 0x00010000u) ? fmaf(cp.z, wl.z, cs.z) : 0.0f;
        a3 += (gs & 0x01000000u) ? fmaf(cp.w, wl.w, cs.w) : 0.0f;
    }

    float* op = out + b * NN + obase + lane * 4;
    atomicAdd(op + 0, a0);
    atomicAdd(op + 1, a1);
    atomicAdd(op + 2, a2);
    atomicAdd(op + 3, a3);
}

// ---------------------------------------------------------------------------
// Launch
// ---------------------------------------------------------------------------
extern "C" void kernel_launch(void* const* d_in, const int* in_sizes, int n_in,
                              void* d_out, int out_size) {
    const float* Xd = (const float*)d_in[0];   // (D,B,N)
    const float* dm = (const float*)d_in[1];   // (D,N,N)
    const float* W  = (const float*)d_in[2];   // (N,N)
    const float* Wl = (const float*)d_in[3];   // (B,N,N)
    const float* F  = (const float*)d_in[4];   // (N,N)
    const float* S  = (const float*)d_in[5];   // (N,N)
    float* out = (float*)d_out;                // (B,N)

    pack_kernel<<<(NN * 32) / 256, 256>>>(Xd, out);   // 256 CTAs

    dim3 grid(NN / OT, NN / ET);                      // 16 x 128 = 2048 CTAs
    fused_kernel<<<grid, 256>>>((const float4*)dm, (const float4*)W, Wl,
                                (const float4*)F, (const float4*)S, out);
}